// round 17
// baseline (speedup 1.0000x reference)
#include <cuda_runtime.h>
#include <cuda_fp16.h>
#include <cstdint>

// ============================================================================
// LSTM cell, two kernels:
//  1) convert: fp32 -> fp16 into __device__ globals (combined [x|h], W per gate)
//  2) GEMM via mma.sync fp16 m16n8k16, cp.async mainloop.
// R16: THREE CTAs per SM (3 warps/SMSP) for stall coverage — the measured
//      binder is warp-level latency coverage, not ldsm restart (R15 null).
//      launch_bounds(128,3) caps regs at 170: single-buffered frags, 2 smem
//      stages, prefetch distance 1 (issue t+1 after sync(t); slot audit safe).
// CTA: 128 thr / 4 warps, warp==gate, warp tile 64x64, BK=32, 64 iters.
// ============================================================================

#define BATCH     8192
#define SA_B      80                          // A smem row stride bytes
#define SB_B      144                         // B smem row stride bytes
#define A_BYTES   (64 * SA_B)                 // 5120
#define BG_BYTES  (32 * SB_B)                 // 4608 per gate
#define STAGE_BYTES (A_BYTES + 4 * BG_BYTES)  // 23552
#define NSTAGES   2
#define SS        260                         // epilogue staging stride (floats)
#define EPI_BYTES (64 * SS * 4)               // 66560
#define SMEM_BYTES EPI_BYTES                  // > 2*STAGE_BYTES (47104)

__device__ static __half A_h[(size_t)BATCH * 2048];      // combined [x|h], 32MB
__device__ static __half W_h[4][(size_t)2048 * 1024];    // per-gate weights, 16MB

// ---------------------------------------------------------------- convert ---
__global__ void __launch_bounds__(256) convert_kernel(
    const float* __restrict__ x, const float* __restrict__ h,
    const float* __restrict__ Wf, const float* __restrict__ Wi,
    const float* __restrict__ Wc, const float* __restrict__ Wo)
{
    const size_t NA = (size_t)BATCH * 2048 / 4;
    const size_t NW = (size_t)2048 * 1024 / 4;
    const size_t total = NA + 4 * NW;
    const size_t stride = (size_t)gridDim.x * blockDim.x;

    for (size_t i = (size_t)blockIdx.x * blockDim.x + threadIdx.x;
         i < total; i += stride) {
        float4 v;
        __half* dst;
        if (i < NA) {
            size_t m = i >> 9;
            size_t k = (i & 511) * 4;
            const float* src = (k < 1024) ? (x + m * 1024 + k)
                                          : (h + m * 1024 + (k - 1024));
            v = *reinterpret_cast<const float4*>(src);
            dst = &A_h[i * 4];
        } else {
            size_t j = i - NA;
            size_t g = j / NW;
            size_t r = j - g * NW;
            const float* Wg = (g == 0) ? Wf : (g == 1) ? Wi : (g == 2) ? Wc : Wo;
            v = *reinterpret_cast<const float4*>(Wg + r * 4);
            dst = &W_h[g][r * 4];
        }
        __half2 lo = __floats2half2_rn(v.x, v.y);
        __half2 hi = __floats2half2_rn(v.z, v.w);
        uint2 out = { *reinterpret_cast<uint32_t*>(&lo), *reinterpret_cast<uint32_t*>(&hi) };
        *reinterpret_cast<uint2*>(dst) = out;
    }
}

// ------------------------------------------------------------------ GEMM ----
__device__ __forceinline__ uint32_t s2u(const void* p) {
    uint32_t a;
    asm("{ .reg .u64 t; cvta.to.shared.u64 t, %1; cvt.u32.u64 %0, t; }"
        : "=r"(a) : "l"(p));
    return a;
}
__device__ __forceinline__ void cp16(uint32_t dst, const __half* src) {
    asm volatile("cp.async.cg.shared.global [%0], [%1], 16;" :: "r"(dst), "l"(src));
}
#define CP_COMMIT() asm volatile("cp.async.commit_group;" ::: "memory")
#define CP_WAIT(n)  asm volatile("cp.async.wait_group %0;" :: "n"(n) : "memory")

__device__ __forceinline__ void ldsm4(uint32_t* r, uint32_t addr) {
    asm volatile("ldmatrix.sync.aligned.m8n8.x4.shared.b16 {%0,%1,%2,%3}, [%4];"
                 : "=r"(r[0]), "=r"(r[1]), "=r"(r[2]), "=r"(r[3]) : "r"(addr));
}
__device__ __forceinline__ void ldsm4t(uint32_t* r, uint32_t addr) {
    asm volatile("ldmatrix.sync.aligned.m8n8.x4.trans.shared.b16 {%0,%1,%2,%3}, [%4];"
                 : "=r"(r[0]), "=r"(r[1]), "=r"(r[2]), "=r"(r[3]) : "r"(addr));
}
__device__ __forceinline__ void mma16(float* d, const uint32_t* a, const uint32_t* b) {
    asm volatile(
        "mma.sync.aligned.m16n8k16.row.col.f32.f16.f16.f32 "
        "{%0,%1,%2,%3}, {%4,%5,%6,%7}, {%8,%9}, {%0,%1,%2,%3};"
        : "+f"(d[0]), "+f"(d[1]), "+f"(d[2]), "+f"(d[3])
        : "r"(a[0]), "r"(a[1]), "r"(a[2]), "r"(a[3]), "r"(b[0]), "r"(b[1]));
}
__device__ __forceinline__ float sigf(float v) {
    return __fdividef(1.0f, 1.0f + __expf(-v));
}
__device__ __forceinline__ float tanhf_e(float v) {
    float ax = fabsf(v);
    float e = __expf(-2.0f * ax);
    float t = __fdividef(1.0f - e, 1.0f + e);
    return copysignf(t, v);
}

// cp.async one BK=32 stage, 128 threads:
// A: 256 chunks (2/thread), B: 1024 chunks (8/thread, gate = c>>1)
__device__ __forceinline__ void load_stage(int T, int tid, uint32_t sb, int m0, int n0)
{
    const uint32_t Ab = sb + (T & (NSTAGES - 1)) * STAGE_BYTES;
    const int k0 = T * 32;
    #pragma unroll
    for (int c = 0; c < 2; c++) {
        int idx = c * 128 + tid;
        int row = idx >> 2, col = idx & 3;
        cp16(Ab + row * SA_B + col * 16,
             &A_h[(size_t)(m0 + row) * 2048 + k0 + col * 8]);
    }
    const uint32_t Bb = Ab + A_BYTES;
    #pragma unroll
    for (int c = 0; c < 8; c++) {
        int g = c >> 1;
        int idx = (c & 1) * 128 + tid;
        int kr = idx >> 3, col = idx & 7;
        cp16(Bb + g * BG_BYTES + kr * SB_B + col * 16,
             &W_h[g][(size_t)(k0 + kr) * 1024 + n0 + col * 8]);
    }
}

__global__ void __launch_bounds__(128, 3)
lstm_mma(const float* __restrict__ cellp,
         const float* __restrict__ bf, const float* __restrict__ bi,
         const float* __restrict__ bc, const float* __restrict__ bo,
         float* __restrict__ outh, float* __restrict__ outc)
{
    extern __shared__ float sm[];
    const uint32_t sb = s2u(sm);

    const int tid  = threadIdx.x;
    const int lane = tid & 31;
    const int g    = tid >> 5;            // warp == gate (0..3)
    const int m0   = blockIdx.x * 64;
    const int n0   = blockIdx.y * 64;

    const int l15  = lane & 15;
    const int ahi  = (lane >> 4) * 16;    // A: 16B k-half select
    const int bhi  = (lane >> 4) * 8;     // B: n-chunk select

    float acc[4][8][4];
    #pragma unroll
    for (int mt = 0; mt < 4; mt++)
        #pragma unroll
        for (int nt = 0; nt < 8; nt++)
            #pragma unroll
            for (int j = 0; j < 4; j++) acc[mt][nt][j] = 0.0f;

    // prologue: stage 0 in flight
    load_stage(0, tid, sb, m0, n0); CP_COMMIT();

    for (int t = 0; t < 64; t++) {
        const int s = t & (NSTAGES - 1);

        CP_WAIT(0);            // own copies of stage t done
        __syncthreads();       // publish stage t; fences slot reuse

        // issue stage t+1 (slot (t+1)%2 = stage t-1's slot; its readers
        // finished before sync(t-1) < sync(t) < here)
        if (t < 63) { load_stage(t + 1, tid, sb, m0, n0); CP_COMMIT(); }

        const uint32_t Ab = sb + s * STAGE_BYTES;
        const uint32_t Bg = Ab + A_BYTES + g * BG_BYTES;

        #pragma unroll
        for (int ks = 0; ks < 2; ks++) {          // two k16 steps (BK=32)
            uint32_t a[4][4];
            #pragma unroll
            for (int mt = 0; mt < 4; mt++)
                ldsm4(a[mt], Ab + (uint32_t)(mt * 16 + l15) * SA_B
                               + (uint32_t)(ks * 32 + ahi));
            uint32_t b[8][2];
            #pragma unroll
            for (int np = 0; np < 4; np++) {
                uint32_t r[4];
                ldsm4t(r, Bg + (uint32_t)(ks * 16 + l15) * SB_B
                             + (uint32_t)(np * 16 + bhi) * 2);
                b[np * 2][0] = r[0]; b[np * 2][1] = r[1];
                b[np * 2 + 1][0] = r[2]; b[np * 2 + 1][1] = r[3];
            }
            #pragma unroll
            for (int mt = 0; mt < 4; mt++)
                #pragma unroll
                for (int nt = 0; nt < 8; nt++)
                    mma16(acc[mt][nt], a[mt], b[nt]);
        }
    }
    __syncthreads();       // mainloop done; smem reused for staging

    // ---- stage gate values through smem (gates live in different warps) ----
    #pragma unroll
    for (int mt = 0; mt < 4; mt++) {
        #pragma unroll
        for (int nt = 0; nt < 8; nt++) {
            int r0 = mt * 16 + (lane >> 2);
            int cb = g * 64 + nt * 8 + (lane & 3) * 2;
            *(float2*)&sm[(size_t)r0 * SS + cb]       = make_float2(acc[mt][nt][0], acc[mt][nt][1]);
            *(float2*)&sm[(size_t)(r0 + 8) * SS + cb] = make_float2(acc[mt][nt][2], acc[mt][nt][3]);
        }
    }
    __syncthreads();

    // ---- fused LSTM combine + store (64 x 64 tile, 32 elems/thread) ----
    const int nl   = tid & 63;
    const int mseg = tid >> 6;            // 0..1
    const int n    = n0 + nl;
    const float Bf = __ldg(bf + n);
    const float Bi = __ldg(bi + n);
    const float Bc = __ldg(bc + n);
    const float Bo = __ldg(bo + n);

    #pragma unroll 4
    for (int r = 0; r < 32; r++) {
        int m = r * 2 + mseg;
        const float* row = &sm[(size_t)m * SS];
        float gf = row[nl]       + Bf;
        float gi = row[64 + nl]  + Bi;
        float gc = row[128 + nl] + Bc;
        float go = row[192 + nl] + Bo;

        float F  = sigf(gf);
        float I  = sigf(gi);
        float O  = sigf(go);
        float CD = tanhf_e(gc);

        size_t gidx = (size_t)(m0 + m) * 1024 + n;
        float cold = __ldg(cellp + gidx);
        float nc = fmaf(F, cold, I * CD);
        float nh = O * tanhf_e(nc);
        outh[gidx] = nh;
        outc[gidx] = nc;
    }
}

extern "C" void kernel_launch(void* const* d_in, const int* in_sizes, int n_in,
                              void* d_out, int out_size)
{
    const float* x    = (const float*)d_in[0];   // [B, 1024]
    const float* h    = (const float*)d_in[1];   // [B, 1024]
    const float* cell = (const float*)d_in[2];   // [B, 1024]
    const float* Wf   = (const float*)d_in[3];   // [2048, 1024]
    const float* bf   = (const float*)d_in[4];
    const float* Wi   = (const float*)d_in[5];
    const float* bi   = (const float*)d_in[6];
    const float* Wc   = (const float*)d_in[7];
    const float* bc   = (const float*)d_in[8];
    const float* Wo   = (const float*)d_in[9];
    const float* bo   = (const float*)d_in[10];

    const int B = in_sizes[0] / 1024;            // 8192

    static bool attr_set = false;
    if (!attr_set) {
        cudaFuncSetAttribute(lstm_mma, cudaFuncAttributeMaxDynamicSharedMemorySize,
                             SMEM_BYTES);
        attr_set = true;
    }

    convert_kernel<<<2048, 256>>>(x, h, Wf, Wi, Wc, Wo);

    float* outh = (float*)d_out;
    float* outc = (float*)d_out + (size_t)B * 1024;

    dim3 grid(B / 64, 16);
    lstm_mma<<<grid, 128, SMEM_BYTES>>>(cell, bf, bi, bc, bo, outh, outc);
}